// round 1
// baseline (speedup 1.0000x reference)
#include <cuda_runtime.h>
#include <cuda_bf16.h>

#define T_LEN 2048
#define VOCAB 1000

// Gate table: for each token, the 32 gate pre-activations (W_ih @ emb[tok] + b_ih + b_hh),
// laid out so that lane g's quad {i_g, f_g, g_g, o_g} is one contiguous float4:
//   tbl[tok*32 + g*4 + q] = gate j = q*8 + g
__device__ float4 d_tbl4[VOCAB * 8];

__global__ void build_table_kernel(const float* __restrict__ emb,
                                   const float* __restrict__ W_ih,
                                   const float* __restrict__ b_ih,
                                   const float* __restrict__ b_hh) {
    int tok = blockIdx.x;
    int j = threadIdx.x;  // gate index 0..31
    __shared__ float e[8];
    if (j < 8) e[j] = emb[tok * 8 + j];
    __syncthreads();
    float s = b_ih[j] + b_hh[j];
#pragma unroll
    for (int k = 0; k < 8; k++)
        s = fmaf(W_ih[j * 8 + k], e[k], s);
    // j = q*8 + g  ->  store at tok*32 + g*4 + q
    int g = j & 7;
    int q = j >> 3;
    reinterpret_cast<float*>(d_tbl4)[tok * 32 + g * 4 + q] = s;
}

__device__ __forceinline__ float tanha(float x) {
    float r;
    asm("tanh.approx.f32 %0, %1;" : "=f"(r) : "f"(x));
    return r;
}

__device__ __forceinline__ float sigm(float x) {
    // sigmoid(x) = 0.5*tanh(0.5x) + 0.5 (exact identity; only tanh.approx error)
    return fmaf(tanha(0.5f * x), 0.5f, 0.5f);
}

__global__ void __launch_bounds__(128)
lstm_scan_kernel(const int* __restrict__ x,
                 const float* __restrict__ W_hh,
                 const float* __restrict__ W_cls,
                 const float* __restrict__ b_cls,
                 float* __restrict__ out) {
    int tid = blockIdx.x * blockDim.x + threadIdx.x;
    int b = tid >> 3;      // batch element
    int g = tid & 7;       // hidden unit owned by this lane

    // W_hh rows for gates {g, g+8, g+16, g+24}, 32 registers
    float w0[8], w1[8], w2[8], w3[8];
#pragma unroll
    for (int k = 0; k < 8; k++) {
        w0[k] = W_hh[(0 * 8 + g) * 8 + k];
        w1[k] = W_hh[(1 * 8 + g) * 8 + k];
        w2[k] = W_hh[(2 * 8 + g) * 8 + k];
        w3[k] = W_hh[(3 * 8 + g) * 8 + k];
    }

    const int4* xr4 = reinterpret_cast<const int4*>(x + (size_t)b * T_LEN);

    float c = 0.0f, h = 0.0f;

    int4 tk = xr4[0];
    float4 xg = __ldg(&d_tbl4[(unsigned)tk.x * 8u + g]);  // prefetched row for t=0

    const int NCHUNK = T_LEN / 4;
    for (int ch = 0; ch < NCHUNK; ch++) {
        int nidx = ch + 1;
        if (nidx >= NCHUNK) nidx = NCHUNK - 1;  // clamped (prefetch garbage is discarded)
        int4 tkn = xr4[nidx];

#pragma unroll
        for (int j = 0; j < 4; j++) {
            // next token (for prefetching the table row used in step t+1)
            int ntok;
            if (j == 0)      ntok = tk.y;
            else if (j == 1) ntok = tk.z;
            else if (j == 2) ntok = tk.w;
            else             ntok = tkn.x;
            float4 xgn = __ldg(&d_tbl4[(unsigned)ntok * 8u + g]);

            // gates = xg + W_hh @ h   (this lane's 4 gate outputs)
            float a0 = xg.x, a1 = xg.y, a2 = xg.z, a3 = xg.w;
#pragma unroll
            for (int k = 0; k < 8; k++) {
                float hk = __shfl_sync(0xffffffffu, h, k, 8);
                a0 = fmaf(w0[k], hk, a0);
                a1 = fmaf(w1[k], hk, a1);
                a2 = fmaf(w2[k], hk, a2);
                a3 = fmaf(w3[k], hk, a3);
            }
            float ig = sigm(a0);
            float fg = sigm(a1);
            float gg = tanha(a2);
            float og = sigm(a3);
            c = fmaf(fg, c, ig * gg);
            h = og * tanha(c);

            xg = xgn;
        }
        tk = tkn;
    }

    // classifier head: out[b] = sigmoid(sum_g h_g * W_cls[g] + b_cls)
    float v = h * W_cls[g];
    v += __shfl_xor_sync(0xffffffffu, v, 4, 8);
    v += __shfl_xor_sync(0xffffffffu, v, 2, 8);
    v += __shfl_xor_sync(0xffffffffu, v, 1, 8);
    if (g == 0) {
        float z = v + b_cls[0];
        out[b] = 1.0f / (1.0f + __expf(-z));
    }
}

extern "C" void kernel_launch(void* const* d_in, const int* in_sizes, int n_in,
                              void* d_out, int out_size) {
    const int*   x     = (const int*)d_in[0];
    const float* emb   = (const float*)d_in[1];
    const float* W_ih  = (const float*)d_in[2];
    const float* W_hh  = (const float*)d_in[3];
    const float* b_ih  = (const float*)d_in[4];
    const float* b_hh  = (const float*)d_in[5];
    const float* W_cls = (const float*)d_in[6];
    const float* b_cls = (const float*)d_in[7];
    float* out = (float*)d_out;

    int B = in_sizes[0] / T_LEN;  // 4096

    build_table_kernel<<<VOCAB, 32>>>(emb, W_ih, b_ih, b_hh);

    int threads = B * 8;
    int block = 128;
    int grid = (threads + block - 1) / block;
    lstm_scan_kernel<<<grid, block>>>(x, W_hh, W_cls, b_cls, out);
}

// round 2
// speedup vs baseline: 1.4226x; 1.4226x over previous
#include <cuda_runtime.h>
#include <cuda_bf16.h>

#define T_LEN 2048
#define VOCAB 1000

// Gate table: for each token, the 32 gate pre-activations (W_ih @ emb[tok] + b_ih + b_hh),
// laid out so lane g's quad {i_g, f_g, g_g, o_g} is one contiguous float4:
//   tbl[tok*8 + g] = (i_g*0.5, f_g*0.5, g_g, o_g*0.5)
// The 0.5 prescale (for the sigmoid gates) is baked in so the chain computes
// sigmoid(x) = fma(tanh.approx(a), 0.5, 0.5) with no extra mul.
__device__ float4 d_tbl4[VOCAB * 8];

__global__ void build_table_kernel(const float* __restrict__ emb,
                                   const float* __restrict__ W_ih,
                                   const float* __restrict__ b_ih,
                                   const float* __restrict__ b_hh) {
    int tok = blockIdx.x;
    int j = threadIdx.x;  // gate index 0..31 (q*8+g, q = i/f/g/o)
    __shared__ float e[8];
    if (j < 8) e[j] = emb[tok * 8 + j];
    __syncthreads();
    float s = b_ih[j] + b_hh[j];
#pragma unroll
    for (int k = 0; k < 8; k++)
        s = fmaf(W_ih[j * 8 + k], e[k], s);
    int g = j & 7;
    int q = j >> 3;
    if (q != 2) s *= 0.5f;  // prescale sigmoid gates (i, f, o)
    reinterpret_cast<float*>(d_tbl4)[tok * 32 + g * 4 + q] = s;
}

__device__ __forceinline__ float tanha(float x) {
    float r;
    asm("tanh.approx.f32 %0, %1;" : "=f"(r) : "f"(x));
    return r;
}

// input already prescaled by 0.5: sigmoid(2a) where a = 0.5*x
__device__ __forceinline__ float sigm_pre(float a) {
    return fmaf(tanha(a), 0.5f, 0.5f);
}

__global__ void __launch_bounds__(256)
lstm_scan_kernel(const int* __restrict__ x,
                 const float* __restrict__ W_hh,
                 const float* __restrict__ W_cls,
                 const float* __restrict__ b_cls,
                 float* __restrict__ out) {
    extern __shared__ float4 stbl[];  // VOCAB*8 float4 = 128 KB

    // cooperative copy of gate table into smem (coalesced 16B loads)
    for (int i = threadIdx.x; i < VOCAB * 8; i += blockDim.x)
        stbl[i] = d_tbl4[i];
    __syncthreads();

    int tid = blockIdx.x * blockDim.x + threadIdx.x;
    int b = tid >> 3;      // batch element
    int g = tid & 7;       // hidden unit owned by this lane

    // W_hh rows for gates {g, g+8, g+16, g+24}; sigmoid rows prescaled by 0.5
    float w0[8], w1[8], w2[8], w3[8];
#pragma unroll
    for (int k = 0; k < 8; k++) {
        w0[k] = 0.5f * W_hh[(0 * 8 + g) * 8 + k];
        w1[k] = 0.5f * W_hh[(1 * 8 + g) * 8 + k];
        w2[k] =        W_hh[(2 * 8 + g) * 8 + k];
        w3[k] = 0.5f * W_hh[(3 * 8 + g) * 8 + k];
    }

    const int4* xr4 = reinterpret_cast<const int4*>(x + (size_t)b * T_LEN);

    float c = 0.0f, h = 0.0f;

    const int NCHUNK = T_LEN / 4;
    int4 cur = xr4[0];
    int4 nxt = xr4[1];
    float4 xg = stbl[(unsigned)cur.x * 8u + g];  // row for t=0

    for (int ch = 0; ch < NCHUNK; ch++) {
        int pf = ch + 2;
        if (pf >= NCHUNK) pf = NCHUNK - 1;  // clamp; garbage prefetch discarded
        int4 nxt2 = xr4[pf];

#pragma unroll
        for (int j = 0; j < 4; j++) {
            int ntok;
            if (j == 0)      ntok = cur.y;
            else if (j == 1) ntok = cur.z;
            else if (j == 2) ntok = cur.w;
            else             ntok = nxt.x;
            float4 xgn = stbl[(unsigned)ntok * 8u + g];  // smem, 1-step prefetch

            // gates = xg + W_hh @ h : split 8-deep chains into 2x4 + add
            float a0 = xg.x, a1 = xg.y, a2 = xg.z, a3 = xg.w;
            float p0 = 0.f, p1 = 0.f, p2 = 0.f, p3 = 0.f;
#pragma unroll
            for (int k = 0; k < 4; k++) {
                float hk = __shfl_sync(0xffffffffu, h, k, 8);
                a0 = fmaf(w0[k], hk, a0);
                a1 = fmaf(w1[k], hk, a1);
                a2 = fmaf(w2[k], hk, a2);
                a3 = fmaf(w3[k], hk, a3);
            }
#pragma unroll
            for (int k = 4; k < 8; k++) {
                float hk = __shfl_sync(0xffffffffu, h, k, 8);
                p0 = fmaf(w0[k], hk, p0);
                p1 = fmaf(w1[k], hk, p1);
                p2 = fmaf(w2[k], hk, p2);
                p3 = fmaf(w3[k], hk, p3);
            }
            a0 += p0; a1 += p1; a2 += p2; a3 += p3;

            float ig = sigm_pre(a0);
            float fg = sigm_pre(a1);
            float gg = tanha(a2);
            float og = sigm_pre(a3);
            c = fmaf(fg, c, ig * gg);
            h = og * tanha(c);

            xg = xgn;
        }
        cur = nxt;
        nxt = nxt2;
    }

    // classifier head: out[b] = sigmoid(sum_g h_g * W_cls[g] + b_cls)
    float v = h * W_cls[g];
    v += __shfl_xor_sync(0xffffffffu, v, 4, 8);
    v += __shfl_xor_sync(0xffffffffu, v, 2, 8);
    v += __shfl_xor_sync(0xffffffffu, v, 1, 8);
    if (g == 0) {
        float z = v + b_cls[0];
        out[b] = 1.0f / (1.0f + __expf(-z));
    }
}

extern "C" void kernel_launch(void* const* d_in, const int* in_sizes, int n_in,
                              void* d_out, int out_size) {
    const int*   x     = (const int*)d_in[0];
    const float* emb   = (const float*)d_in[1];
    const float* W_ih  = (const float*)d_in[2];
    const float* W_hh  = (const float*)d_in[3];
    const float* b_ih  = (const float*)d_in[4];
    const float* b_hh  = (const float*)d_in[5];
    const float* W_cls = (const float*)d_in[6];
    const float* b_cls = (const float*)d_in[7];
    float* out = (float*)d_out;

    int B = in_sizes[0] / T_LEN;  // 4096

    build_table_kernel<<<VOCAB, 32>>>(emb, W_ih, b_ih, b_hh);

    size_t smem = (size_t)VOCAB * 8 * sizeof(float4);  // 128000 B
    static int attr_set = 0;
    // setting a function attribute is idempotent and not a stream op; safe under capture
    cudaFuncSetAttribute(lstm_scan_kernel,
                         cudaFuncAttributeMaxDynamicSharedMemorySize, (int)smem);
    (void)attr_set;

    int threads = B * 8;            // 32768
    int block = 256;
    int grid = threads / block;     // 128 blocks, 1 per SM, single wave
    lstm_scan_kernel<<<grid, block, smem>>>(x, W_hh, W_cls, b_cls, out);
}